// round 14
// baseline (speedup 1.0000x reference)
#include <cuda_runtime.h>
#include <cuda_bf16.h>
#include <cuda_fp16.h>
#include <cstdint>

// ---------------------------------------------------------------------------
// GCNModel: GCN(256)+BN+LReLU+res -> GAT(4x64,mean)+BN+LReLU+res ->
//           GCN(64->16)+BN+LReLU+res -> GCN(16->64) -> Linear(64->64)
// N=50000, E=800000. edge_index int32.
// Big GEMMs + res2: mma.sync bf16 hi/lo split (K_eff=768), staged A2.
// h1/h2 stored fp16 (gather payload compression). CSR gather, unroll x2.
// 3-phase parallel scan. Stream fork-join overlap. Layer4+proj fused.
// ---------------------------------------------------------------------------

typedef int eidx_t;

#define NMAX 50000
#define EMAX 800000

__device__ __align__(16) float g_P0[NMAX * 256];
__device__ __align__(16) float g_P1[NMAX * 256];
__device__ __align__(16) float g_P2[NMAX * 256];
__device__ __align__(16) float g_P3[NMAX * 256];
__device__ __align__(16) __half g_H16[NMAX * 256];
__device__ float g_dinv[NMAX];
__device__ int   g_degi[NMAX];
__device__ int   g_csr_ptr[NMAX + 1];
__device__ int   g_csr_cnt[NMAX];
__device__ int   g_csr_src[EMAX];
__device__ int   g_blocksum[256];
__device__ int   g_bloff[256];
__device__ __align__(16) float g_als[NMAX * 4];
__device__ __align__(16) float g_ald[NMAX * 4];
__device__ __align__(16) float g_eself[NMAX * 4];
__device__ float g_bnsum[512];
__device__ float g_bnsq[512];
__device__ float g_bnscale[512];
__device__ float g_bnshift[512];
__device__ __align__(16) float g_W4p[16 * 64];
__device__ __align__(16) float g_b4p[64];

// bf16 split operands ([hi|hi|lo] for A, [hi|lo|hi] for B^T; slot3 = r2W padded)
__device__ __align__(16) __nv_bfloat16 g_A2[(size_t)50048 * 768];
__device__ __align__(16) __nv_bfloat16 g_Bt2[4][256 * 768];

// ---- helpers --------------------------------------------------------------

__device__ __forceinline__ float lrelu2(float x) { return x > 0.f ? x : 0.2f * x; }

__device__ __forceinline__ void ldsm4(uint32_t* r, uint32_t addr) {
    asm volatile("ldmatrix.sync.aligned.m8n8.x4.shared.b16 {%0,%1,%2,%3}, [%4];"
                 : "=r"(r[0]), "=r"(r[1]), "=r"(r[2]), "=r"(r[3]) : "r"(addr));
}

__device__ __forceinline__ void mma16816(float* c, const uint32_t* a,
                                         uint32_t b0, uint32_t b1) {
    asm volatile(
        "mma.sync.aligned.m16n8k16.row.col.f32.bf16.bf16.f32 "
        "{%0,%1,%2,%3}, {%4,%5,%6,%7}, {%8,%9}, {%0,%1,%2,%3};"
        : "+f"(c[0]), "+f"(c[1]), "+f"(c[2]), "+f"(c[3])
        : "r"(a[0]), "r"(a[1]), "r"(a[2]), "r"(a[3]), "r"(b0), "r"(b1));
}

__device__ __forceinline__ void unp8(uint4 v, float* f) {
    float2 t;
    t = __half22float2(*(__half2*)&v.x); f[0] = t.x; f[1] = t.y;
    t = __half22float2(*(__half2*)&v.y); f[2] = t.x; f[3] = t.y;
    t = __half22float2(*(__half2*)&v.z); f[4] = t.x; f[5] = t.y;
    t = __half22float2(*(__half2*)&v.w); f[6] = t.x; f[7] = t.y;
}

// ---- init: zero degree/csr counters + all BN accumulators -----------------

__global__ void k_init(int n) {
    int i = blockIdx.x * blockDim.x + threadIdx.x;
    if (i < n) { g_degi[i] = 0; g_csr_cnt[i] = 0; }
    if (i < 512) { g_bnsum[i] = 0.f; g_bnsq[i] = 0.f; }
}

// ---- CSR build ------------------------------------------------------------

__global__ void k_hist(const eidx_t* __restrict__ ei, int E) {
    int e = blockIdx.x * blockDim.x + threadIdx.x;
    if (e < E) atomicAdd(&g_degi[(int)ei[E + e]], 1);
}

__global__ void k_dinv(int n) {
    int i = blockIdx.x * blockDim.x + threadIdx.x;
    if (i < n) g_dinv[i] = rsqrtf((float)g_degi[i] + 1.0f);
}

// 3-phase scan: per-block excl scan -> scan block sums -> add offsets
__global__ void k_scan1(int n) {
    __shared__ int sh[256];
    int tid = threadIdx.x;
    int i = blockIdx.x * 256 + tid;
    int v = (i < n) ? g_degi[i] : 0;
    sh[tid] = v;
    __syncthreads();
#pragma unroll
    for (int off = 1; off < 256; off <<= 1) {
        int t = (tid >= off) ? sh[tid - off] : 0;
        __syncthreads();
        sh[tid] += t;
        __syncthreads();
    }
    if (i < n) g_csr_ptr[i] = sh[tid] - v;   // exclusive
    if (tid == 255) g_blocksum[blockIdx.x] = sh[255];
}

__global__ void k_scan2(int nb, int n) {
    __shared__ int sh[256];
    int tid = threadIdx.x;
    int v = (tid < nb) ? g_blocksum[tid] : 0;
    sh[tid] = v;
    __syncthreads();
#pragma unroll
    for (int off = 1; off < 256; off <<= 1) {
        int t = (tid >= off) ? sh[tid - off] : 0;
        __syncthreads();
        sh[tid] += t;
        __syncthreads();
    }
    g_bloff[tid] = sh[tid] - v;              // exclusive
    if (tid == nb - 1) g_csr_ptr[n] = sh[tid];
}

__global__ void k_scan3(int n) {
    int i = blockIdx.x * blockDim.x + threadIdx.x;
    if (i < n) g_csr_ptr[i] += g_bloff[i >> 8];
}

__global__ void k_fill(const eidx_t* __restrict__ ei, int E) {
    int e = blockIdx.x * blockDim.x + threadIdx.x;
    if (e >= E) return;
    int dst = (int)ei[E + e];
    int pos = g_csr_ptr[dst] + atomicAdd(&g_csr_cnt[dst], 1);
    g_csr_src[pos] = (int)ei[e];
}

// ---- fused layer4 weights: W4p = W4 @ pW ; b4p = b4 @ pW + pb -------------

__global__ void k_w4comb(const float* __restrict__ W4, const float* __restrict__ pW,
                         const float* __restrict__ b4, const float* __restrict__ pb) {
    int m = threadIdx.x;   // 64
    int k = blockIdx.x;    // 0..16
    if (k < 16) {
        float s = 0.f;
        for (int j = 0; j < 64; j++) s += W4[k * 64 + j] * pW[j * 64 + m];
        g_W4p[k * 64 + m] = s;
    } else {
        float s = pb[m];
        for (int j = 0; j < 64; j++) s += b4[j] * pW[j * 64 + m];
        g_b4p[m] = s;
    }
}

// ---- split builders -------------------------------------------------------

__global__ void k_buildA(const float* __restrict__ X, __nv_bfloat16* __restrict__ A2,
                         long long total) {
    long long i = (long long)blockIdx.x * blockDim.x + threadIdx.x;
    if (i >= total) return;
    int r = (int)(i >> 8), k = (int)(i & 255);
    float v = X[i];
    __nv_bfloat16 h = __float2bfloat16(v);
    __nv_bfloat16 l = __float2bfloat16(v - __bfloat162float(h));
    size_t b = (size_t)r * 768 + k;
    A2[b] = h;
    A2[b + 256] = h;
    A2[b + 512] = l;
}

__global__ void k_buildB(const float* __restrict__ W, __nv_bfloat16* __restrict__ Bt) {
    int idx = blockIdx.x * blockDim.x + threadIdx.x;  // 65536
    int m = idx >> 8, k = idx & 255;
    float v = W[k * 256 + m];
    __nv_bfloat16 h = __float2bfloat16(v);
    __nv_bfloat16 l = __float2bfloat16(v - __bfloat162float(h));
    size_t b = (size_t)m * 768 + k;
    Bt[b] = h;
    Bt[b + 256] = l;
    Bt[b + 512] = h;
}

__global__ void k_buildB64(const float* __restrict__ W, __nv_bfloat16* __restrict__ Bt) {
    int idx = blockIdx.x * blockDim.x + threadIdx.x;  // 32768
    int m = idx >> 8, k = idx & 255;
    float v = (m < 64) ? W[k * 64 + m] : 0.0f;
    __nv_bfloat16 h = __float2bfloat16(v);
    __nv_bfloat16 l = __float2bfloat16(v - __bfloat162float(h));
    size_t b = (size_t)m * 768 + k;
    Bt[b] = h;
    Bt[b + 256] = l;
    Bt[b + 512] = h;
}

// ---- mma.sync bf16 GEMM: out = A2[n,768] @ Bt2[.,768]^T (+bias) -----------
// Cf: fp32 output (nullable). Ch: fp16 output (nullable). Exactly one set.

#define MSTRIDE 80
#define MTILEB (128 * MSTRIDE)

__global__ __launch_bounds__(256)
void k_mma_gemm(const __nv_bfloat16* __restrict__ A2, const __nv_bfloat16* __restrict__ Bt2,
                const float* __restrict__ bias, float* __restrict__ Cf,
                __half* __restrict__ Ch, int n, int M) {
    __shared__ __align__(16) unsigned char As[2][MTILEB];
    __shared__ __align__(16) unsigned char Bs[2][MTILEB];

    int tid = threadIdx.x, lane = tid & 31, warp = tid >> 5;
    int wm = warp & 1, wn = warp >> 1;
    int row0 = blockIdx.y * 128, col0 = blockIdx.x * 128;

    int v0 = tid * 2, v1 = v0 + 1;
    int ar0 = v0 >> 2, ac0 = v0 & 3;
    int ar1 = v1 >> 2, ac1 = v1 & 3;
    int rA0 = row0 + ar0; rA0 = rA0 < n ? rA0 : n - 1;
    int rA1 = row0 + ar1; rA1 = rA1 < n ? rA1 : n - 1;
    const __nv_bfloat16* pA0 = A2 + (size_t)rA0 * 768 + ac0 * 8;
    const __nv_bfloat16* pA1 = A2 + (size_t)rA1 * 768 + ac1 * 8;
    const __nv_bfloat16* pB0 = Bt2 + (size_t)(col0 + ar0) * 768 + ac0 * 8;
    const __nv_bfloat16* pB1 = Bt2 + (size_t)(col0 + ar1) * 768 + ac1 * 8;

    uint32_t asb = (uint32_t)__cvta_generic_to_shared(As);
    uint32_t bsb = (uint32_t)__cvta_generic_to_shared(Bs);

    float acc[4][4][4];
#pragma unroll
    for (int t = 0; t < 4; t++)
#pragma unroll
        for (int j = 0; j < 4; j++)
#pragma unroll
            for (int q = 0; q < 4; q++) acc[t][j][q] = 0.0f;

    const int KT = 24;
    uint4 ra0, ra1, rb0, rb1;

    ra0 = *(const uint4*)pA0;
    ra1 = *(const uint4*)pA1;
    rb0 = *(const uint4*)pB0;
    rb1 = *(const uint4*)pB1;
    *(uint4*)(As[0] + ar0 * MSTRIDE + ac0 * 16) = ra0;
    *(uint4*)(As[0] + ar1 * MSTRIDE + ac1 * 16) = ra1;
    *(uint4*)(Bs[0] + ar0 * MSTRIDE + ac0 * 16) = rb0;
    *(uint4*)(Bs[0] + ar1 * MSTRIDE + ac1 * 16) = rb1;
    __syncthreads();

    for (int kt = 0; kt < KT; kt++) {
        int buf = kt & 1;
        if (kt + 1 < KT) {
            int off = (kt + 1) * 32;
            ra0 = *(const uint4*)(pA0 + off);
            ra1 = *(const uint4*)(pA1 + off);
            rb0 = *(const uint4*)(pB0 + off);
            rb1 = *(const uint4*)(pB1 + off);
        }
        uint32_t ab = asb + buf * MTILEB;
        uint32_t bb = bsb + buf * MTILEB;
#pragma unroll
        for (int s = 0; s < 2; s++) {
            uint32_t a[4][4];
            uint32_t br[2][4];
#pragma unroll
            for (int t = 0; t < 4; t++) {
                uint32_t ad = ab + (uint32_t)((wm * 64 + t * 16 + (lane & 15)) * MSTRIDE +
                                              (s * 16 + (lane >> 4) * 8) * 2);
                ldsm4(a[t], ad);
            }
#pragma unroll
            for (int p = 0; p < 2; p++) {
                uint32_t bd = bb + (uint32_t)((wn * 32 + p * 16 + (lane & 7) + (lane >> 4) * 8) * MSTRIDE +
                                              (s * 16 + ((lane >> 3) & 1) * 8) * 2);
                ldsm4(br[p], bd);
            }
#pragma unroll
            for (int t = 0; t < 4; t++)
#pragma unroll
                for (int j = 0; j < 4; j++)
                    mma16816(acc[t][j], a[t], br[j >> 1][(j & 1) * 2],
                             br[j >> 1][(j & 1) * 2 + 1]);
        }
        if (kt + 1 < KT) {
            int nb = (kt + 1) & 1;
            *(uint4*)(As[nb] + ar0 * MSTRIDE + ac0 * 16) = ra0;
            *(uint4*)(As[nb] + ar1 * MSTRIDE + ac1 * 16) = ra1;
            *(uint4*)(Bs[nb] + ar0 * MSTRIDE + ac0 * 16) = rb0;
            *(uint4*)(Bs[nb] + ar1 * MSTRIDE + ac1 * 16) = rb1;
        }
        __syncthreads();
    }

#pragma unroll
    for (int t = 0; t < 4; t++) {
        int r1 = row0 + wm * 64 + t * 16 + (lane >> 2);
        int r2 = r1 + 8;
#pragma unroll
        for (int j = 0; j < 4; j++) {
            int c = col0 + wn * 32 + j * 8 + (lane & 3) * 2;
            if (c >= M) continue;
            float bx = bias ? bias[c] : 0.f;
            float by = bias ? bias[c + 1] : 0.f;
            if (Ch) {
                if (r1 < n)
                    *(__half2*)(Ch + (size_t)r1 * M + c) =
                        __floats2half2_rn(acc[t][j][0] + bx, acc[t][j][1] + by);
                if (r2 < n)
                    *(__half2*)(Ch + (size_t)r2 * M + c) =
                        __floats2half2_rn(acc[t][j][2] + bx, acc[t][j][3] + by);
            } else {
                if (r1 < n) {
                    float2 v = make_float2(acc[t][j][0] + bx, acc[t][j][1] + by);
                    *(float2*)(Cf + (size_t)r1 * M + c) = v;
                }
                if (r2 < n) {
                    float2 v = make_float2(acc[t][j][2] + bx, acc[t][j][3] + by);
                    *(float2*)(Cf + (size_t)r2 * M + c) = v;
                }
            }
        }
    }
}

// ---- small SGEMM (64x64 tile) for M<=64 outputs ---------------------------

#define BM 64
#define BN 64
#define BKK 16

__global__ void k_sgemm(const float* __restrict__ A, const float* __restrict__ B,
                        const float* __restrict__ bias, float* __restrict__ C,
                        int n, int K, int M) {
    __shared__ __align__(16) float As[BKK][BM];
    __shared__ __align__(16) float Bs[BKK][BN];
    int tid = threadIdx.x;
    int tx = tid & 15, ty = tid >> 4;
    int row0 = blockIdx.y * BM;
    int col0 = blockIdx.x * BN;
    int ar = tid >> 2, ak4 = (tid & 3) * 4;
    int bk = tid >> 4, bc = (tid & 15) * 4;

    float acc[4][4];
#pragma unroll
    for (int i = 0; i < 4; i++)
#pragma unroll
        for (int j = 0; j < 4; j++) acc[i][j] = 0.0f;

    for (int k0 = 0; k0 < K; k0 += BKK) {
        float4 av = make_float4(0.f, 0.f, 0.f, 0.f);
        if (row0 + ar < n)
            av = *(const float4*)(A + (long long)(row0 + ar) * K + k0 + ak4);
        As[ak4 + 0][ar] = av.x;
        As[ak4 + 1][ar] = av.y;
        As[ak4 + 2][ar] = av.z;
        As[ak4 + 3][ar] = av.w;

        float4 bv = make_float4(0.f, 0.f, 0.f, 0.f);
        if (col0 + bc < M)
            bv = *(const float4*)(B + (long long)(k0 + bk) * M + col0 + bc);
        *(float4*)&Bs[bk][bc] = bv;

        __syncthreads();
#pragma unroll
        for (int k = 0; k < BKK; k++) {
            float4 a4 = *(const float4*)&As[k][ty * 4];
            float4 b4 = *(const float4*)&Bs[k][tx * 4];
            float ar_[4] = {a4.x, a4.y, a4.z, a4.w};
            float br_[4] = {b4.x, b4.y, b4.z, b4.w};
#pragma unroll
            for (int i = 0; i < 4; i++)
#pragma unroll
                for (int j = 0; j < 4; j++)
                    acc[i][j] = fmaf(ar_[i], br_[j], acc[i][j]);
        }
        __syncthreads();
    }

#pragma unroll
    for (int i = 0; i < 4; i++) {
        int r = row0 + ty * 4 + i;
        if (r >= n) continue;
#pragma unroll
        for (int j = 0; j < 4; j++) {
            int c = col0 + tx * 4 + j;
            if (c < M) {
                float bv = bias ? bias[c] : 0.0f;
                C[(long long)r * M + c] = acc[i][j] + bv;
            }
        }
    }
}

// ---- GCN gather fp32 (D=16 layers), unroll x2, bias nullable --------------

template <int D>
__global__ void k_gcn_gather(const float* __restrict__ H, const float* __restrict__ b,
                             float* __restrict__ OUT, int n) {
    constexpr int L4 = D / 4;
    constexpr int T4 = (L4 < 32) ? L4 : 32;
    constexpr int V4 = L4 / T4;
    long long gt = (long long)blockIdx.x * blockDim.x + threadIdx.x;
    int node = (int)(gt / T4);
    int sub = (int)(gt % T4);
    if (node >= n) return;
    float dv = g_dinv[node];
    float self = dv * dv;
    const float4* hn = (const float4*)(H + (size_t)node * D);
    const float4* bb = (const float4*)b;
    float4 acc[V4];
#pragma unroll
    for (int v = 0; v < V4; v++) {
        int idx = sub + v * T4;
        float4 h = hn[idx];
        float4 bv = b ? bb[idx] : make_float4(0.f, 0.f, 0.f, 0.f);
        acc[v] = make_float4(h.x * self + bv.x, h.y * self + bv.y,
                             h.z * self + bv.z, h.w * self + bv.w);
    }
    int beg = g_csr_ptr[node], end = g_csr_ptr[node + 1];
    int p = beg;
    for (; p + 2 <= end; p += 2) {
        int s0 = g_csr_src[p];
        int s1 = g_csr_src[p + 1];
        float n0 = g_dinv[s0] * dv;
        float n1 = g_dinv[s1] * dv;
        const float4* h0 = (const float4*)(H + (size_t)s0 * D);
        const float4* h1 = (const float4*)(H + (size_t)s1 * D);
#pragma unroll
        for (int v = 0; v < V4; v++) {
            float4 a = h0[sub + v * T4];
            float4 c = h1[sub + v * T4];
            acc[v].x = fmaf(a.x, n0, acc[v].x);
            acc[v].y = fmaf(a.y, n0, acc[v].y);
            acc[v].z = fmaf(a.z, n0, acc[v].z);
            acc[v].w = fmaf(a.w, n0, acc[v].w);
            acc[v].x = fmaf(c.x, n1, acc[v].x);
            acc[v].y = fmaf(c.y, n1, acc[v].y);
            acc[v].z = fmaf(c.z, n1, acc[v].z);
            acc[v].w = fmaf(c.w, n1, acc[v].w);
        }
    }
    if (p < end) {
        int s0 = g_csr_src[p];
        float n0 = g_dinv[s0] * dv;
        const float4* h0 = (const float4*)(H + (size_t)s0 * D);
#pragma unroll
        for (int v = 0; v < V4; v++) {
            float4 a = h0[sub + v * T4];
            acc[v].x = fmaf(a.x, n0, acc[v].x);
            acc[v].y = fmaf(a.y, n0, acc[v].y);
            acc[v].z = fmaf(a.z, n0, acc[v].z);
            acc[v].w = fmaf(a.w, n0, acc[v].w);
        }
    }
    float4* op = (float4*)(OUT + (size_t)node * D);
#pragma unroll
    for (int v = 0; v < V4; v++) op[sub + v * T4] = acc[v];
}

// ---- GCN gather fp16 payload (D=256): thread sub handles cols sub*8..+7 ---

__global__ void k_gcn_gather_h(const __half* __restrict__ H, const float* __restrict__ b,
                               float* __restrict__ OUT, int n) {
    long long gt = (long long)blockIdx.x * blockDim.x + threadIdx.x;
    int node = (int)(gt >> 5);
    int sub = (int)(gt & 31);
    if (node >= n) return;
    float dv = g_dinv[node];
    float self = dv * dv;
    float a[8], acc[8];
    unp8(((const uint4*)(H + (size_t)node * 256))[sub], a);
    float4 b0 = ((const float4*)b)[sub * 2];
    float4 b1 = ((const float4*)b)[sub * 2 + 1];
    acc[0] = a[0] * self + b0.x; acc[1] = a[1] * self + b0.y;
    acc[2] = a[2] * self + b0.z; acc[3] = a[3] * self + b0.w;
    acc[4] = a[4] * self + b1.x; acc[5] = a[5] * self + b1.y;
    acc[6] = a[6] * self + b1.z; acc[7] = a[7] * self + b1.w;

    int beg = g_csr_ptr[node], end = g_csr_ptr[node + 1];
    int p = beg;
    for (; p + 2 <= end; p += 2) {
        int s0 = g_csr_src[p];
        int s1 = g_csr_src[p + 1];
        float n0 = g_dinv[s0] * dv;
        float n1 = g_dinv[s1] * dv;
        float f0[8], f1[8];
        unp8(((const uint4*)(H + (size_t)s0 * 256))[sub], f0);
        unp8(((const uint4*)(H + (size_t)s1 * 256))[sub], f1);
#pragma unroll
        for (int j = 0; j < 8; j++) {
            acc[j] = fmaf(f0[j], n0, acc[j]);
            acc[j] = fmaf(f1[j], n1, acc[j]);
        }
    }
    if (p < end) {
        int s0 = g_csr_src[p];
        float n0 = g_dinv[s0] * dv;
        float f0[8];
        unp8(((const uint4*)(H + (size_t)s0 * 256))[sub], f0);
#pragma unroll
        for (int j = 0; j < 8; j++) acc[j] = fmaf(f0[j], n0, acc[j]);
    }
    float4* op = (float4*)(OUT + (size_t)node * 256);
    op[sub * 2] = make_float4(acc[0], acc[1], acc[2], acc[3]);
    op[sub * 2 + 1] = make_float4(acc[4], acc[5], acc[6], acc[7]);
}

// ---- BatchNorm (pointer-parameterized) ------------------------------------

__global__ void k_bn_stats(const float* __restrict__ X, float* __restrict__ bnsum,
                           float* __restrict__ bnsq, int n, int C) {
    int c = threadIdx.x;
    long long r0 = (long long)blockIdx.x * 256;
    long long r1 = r0 + 256;
    if (r1 > n) r1 = n;
    float s = 0.f, q = 0.f;
    for (long long r = r0; r < r1; r++) {
        float v = X[r * C + c];
        s += v;
        q += v * v;
    }
    atomicAdd(&bnsum[c], s);
    atomicAdd(&bnsq[c], q);
}

__global__ void k_bn_finalize(const float* __restrict__ g, const float* __restrict__ be,
                              const float* __restrict__ bnsum, const float* __restrict__ bnsq,
                              float* __restrict__ scale, float* __restrict__ shift,
                              float invn, int C) {
    int c = blockIdx.x * blockDim.x + threadIdx.x;
    if (c >= C) return;
    float mean = bnsum[c] * invn;
    float var = bnsq[c] * invn - mean * mean;
    float r = rsqrtf(var + 1e-5f);
    float sc = g[c] * r;
    scale[c] = sc;
    shift[c] = be[c] - mean * sc;
}

__global__ void k_bn_apply_add(const float* __restrict__ X, const float* __restrict__ R,
                               const float* __restrict__ scale, const float* __restrict__ shift,
                               float* __restrict__ OUT, long long total, int C) {
    long long i = (long long)blockIdx.x * blockDim.x + threadIdx.x;
    if (i >= total) return;
    int c = (int)(i % C);
    float v = fmaf(X[i], scale[c], shift[c]);
    v = v > 0.f ? v : 0.01f * v;
    OUT[i] = v + R[i];
}

// layer-1 epilogue: x2 only needed as bf16 split -> write A2 only
__global__ void k_bn_apply_add_split(const float* __restrict__ X, const float* __restrict__ R,
                                     const float* __restrict__ scale, const float* __restrict__ shift,
                                     __nv_bfloat16* __restrict__ A2, long long total) {
    long long i = (long long)blockIdx.x * blockDim.x + threadIdx.x;
    if (i >= total) return;
    int c = (int)(i & 255);
    int r = (int)(i >> 8);
    float v = fmaf(X[i], scale[c], shift[c]);
    v = v > 0.f ? v : 0.01f * v;
    v += R[i];
    __nv_bfloat16 h = __float2bfloat16(v);
    __nv_bfloat16 l = __float2bfloat16(v - __bfloat162float(h));
    size_t b = (size_t)r * 768 + c;
    A2[b] = h;
    A2[b + 256] = h;
    A2[b + 512] = l;
}

// ---- GAT (fp16 H2) --------------------------------------------------------

__global__ void k_gat_logits(const __half* __restrict__ H2, const float* __restrict__ a_s,
                             const float* __restrict__ a_d, int n) {
    __shared__ float sa[256], sd[256];
    sa[threadIdx.x] = a_s[threadIdx.x];
    sd[threadIdx.x] = a_d[threadIdx.x];
    __syncthreads();
    int gw = (int)(((long long)blockIdx.x * blockDim.x + threadIdx.x) >> 5);
    int lane = threadIdx.x & 31;
    if (gw >= n) return;
    float h[8];
    unp8(((const uint4*)(H2 + (size_t)gw * 256))[lane], h);
    int base = lane * 8;
    float ps = 0.f, pd = 0.f;
#pragma unroll
    for (int j = 0; j < 8; j++) {
        ps = fmaf(h[j], sa[base + j], ps);
        pd = fmaf(h[j], sd[base + j], pd);
    }
#pragma unroll
    for (int off = 4; off; off >>= 1) {
        ps += __shfl_down_sync(0xffffffffu, ps, off);
        pd += __shfl_down_sync(0xffffffffu, pd, off);
    }
    if ((lane & 7) == 0) {
        int hh = lane >> 3;
        g_als[gw * 4 + hh] = ps;
        g_ald[gw * 4 + hh] = pd;
        g_eself[gw * 4 + hh] = lrelu2(ps + pd);
    }
}

__global__ void k_gat_gather(const __half* __restrict__ H2, const float* __restrict__ bg,
                             float* __restrict__ OUT, int n) {
    long long gt = (long long)blockIdx.x * blockDim.x + threadIdx.x;
    int node = (int)(gt >> 5);
    int lane = threadIdx.x & 31;
    if (node >= n) return;
    int h = lane >> 3;
    int beg = g_csr_ptr[node], end = g_csr_ptr[node + 1];

    float ald_h = 0.f, es = 0.f, denom = 0.f;
    if (lane < 4) {
        ald_h = g_ald[node * 4 + lane];
        es = expf(g_eself[node * 4 + lane]);
        denom = es;
    }
    float w0 = __shfl_sync(0xffffffffu, es, h);

    float a[8], acc[8];
    unp8(((const uint4*)(H2 + (size_t)node * 256))[lane], a);
#pragma unroll
    for (int j = 0; j < 8; j++) acc[j] = a[j] * w0;

    int p = beg;
    for (; p + 2 <= end; p += 2) {
        int s0 = g_csr_src[p];
        int s1 = g_csr_src[p + 1];
        float e0 = 0.f, e1 = 0.f;
        if (lane < 4) {
            e0 = expf(lrelu2(g_als[s0 * 4 + lane] + ald_h));
            e1 = expf(lrelu2(g_als[s1 * 4 + lane] + ald_h));
            denom += e0 + e1;
        }
        float wa = __shfl_sync(0xffffffffu, e0, h);
        float wb = __shfl_sync(0xffffffffu, e1, h);
        float f0[8], f1[8];
        unp8(((const uint4*)(H2 + (size_t)s0 * 256))[lane], f0);
        unp8(((const uint4*)(H2 + (size_t)s1 * 256))[lane], f1);
#pragma unroll
        for (int j = 0; j < 8; j++) {
            acc[j] = fmaf(f0[j], wa, acc[j]);
            acc[j] = fmaf(f1[j], wb, acc[j]);
        }
    }
    if (p < end) {
        int s0 = g_csr_src[p];
        float e0 = 0.f;
        if (lane < 4) {
            e0 = expf(lrelu2(g_als[s0 * 4 + lane] + ald_h));
            denom += e0;
        }
        float wa = __shfl_sync(0xffffffffu, e0, h);
        float f0[8];
        unp8(((const uint4*)(H2 + (size_t)s0 * 256))[lane], f0);
#pragma unroll
        for (int j = 0; j < 8; j++) acc[j] = fmaf(f0[j], wa, acc[j]);
    }

    float dh = __shfl_sync(0xffffffffu, denom, h);
    float inv = 1.0f / dh;
    float v[8];
#pragma unroll
    for (int j = 0; j < 8; j++) {
        v[j] = acc[j] * inv;
        v[j] += __shfl_xor_sync(0xffffffffu, v[j], 8);
        v[j] += __shfl_xor_sync(0xffffffffu, v[j], 16);
    }
    if (lane < 8) {
        int d0 = lane * 8;
        float4 o0 = make_float4(0.25f * v[0] + bg[d0 + 0], 0.25f * v[1] + bg[d0 + 1],
                                0.25f * v[2] + bg[d0 + 2], 0.25f * v[3] + bg[d0 + 3]);
        float4 o1 = make_float4(0.25f * v[4] + bg[d0 + 4], 0.25f * v[5] + bg[d0 + 5],
                                0.25f * v[6] + bg[d0 + 6], 0.25f * v[7] + bg[d0 + 7]);
        float4* op = (float4*)(OUT + (size_t)node * 64 + d0);
        op[0] = o0;
        op[1] = o1;
    }
}

// ---------------------------------------------------------------------------
// host
// ---------------------------------------------------------------------------

static inline unsigned gb(long long total, int block) {
    return (unsigned)((total + block - 1) / block);
}

extern "C" void kernel_launch(void* const* d_in, const int* in_sizes, int n_in,
                              void* d_out, int out_size) {
    const float* x    = (const float*)d_in[0];
    const eidx_t* ei  = (const eidx_t*)d_in[1];
    const float* W1   = (const float*)d_in[2];
    const float* b1   = (const float*)d_in[3];
    const float* g1   = (const float*)d_in[4];
    const float* be1  = (const float*)d_in[5];
    const float* Wg   = (const float*)d_in[6];
    const float* a_s  = (const float*)d_in[7];
    const float* a_d  = (const float*)d_in[8];
    const float* bg   = (const float*)d_in[9];
    const float* g2   = (const float*)d_in[10];
    const float* be2  = (const float*)d_in[11];
    const float* W3   = (const float*)d_in[12];
    const float* b3   = (const float*)d_in[13];
    const float* g3   = (const float*)d_in[14];
    const float* be3  = (const float*)d_in[15];
    const float* W4   = (const float*)d_in[16];
    const float* b4   = (const float*)d_in[17];
    const float* r1W  = (const float*)d_in[18];
    const float* r1b  = (const float*)d_in[19];
    const float* r2W  = (const float*)d_in[20];
    const float* r2b  = (const float*)d_in[21];
    const float* r3W  = (const float*)d_in[22];
    const float* r3b  = (const float*)d_in[23];
    const float* pW   = (const float*)d_in[24];
    const float* pb   = (const float*)d_in[25];
    float* out = (float*)d_out;

    int N = in_sizes[0] / 256;
    int E = in_sizes[1] / 2;
    float invn = 1.0f / (float)N;

    float *P0, *P1, *P2, *P3, *bnsum, *bnsq, *bnscale, *bnshift, *W4p, *b4p;
    __half* H16;
    __nv_bfloat16 *A2, *Bt2;
    cudaGetSymbolAddress((void**)&P0, g_P0);
    cudaGetSymbolAddress((void**)&P1, g_P1);
    cudaGetSymbolAddress((void**)&P2, g_P2);
    cudaGetSymbolAddress((void**)&P3, g_P3);
    cudaGetSymbolAddress((void**)&H16, g_H16);
    cudaGetSymbolAddress((void**)&bnsum, g_bnsum);
    cudaGetSymbolAddress((void**)&bnsq, g_bnsq);
    cudaGetSymbolAddress((void**)&bnscale, g_bnscale);
    cudaGetSymbolAddress((void**)&bnshift, g_bnshift);
    cudaGetSymbolAddress((void**)&W4p, g_W4p);
    cudaGetSymbolAddress((void**)&b4p, g_b4p);
    cudaGetSymbolAddress((void**)&A2, g_A2);
    cudaGetSymbolAddress((void**)&Bt2, g_Bt2);

    static cudaStream_t s1 = nullptr, s2 = nullptr;
    static cudaEvent_t evSetup, evCSR, evA, evRes1, evX2, evRes2, evX3, evRes3;
    if (!s1) {
        cudaStreamCreateWithFlags(&s1, cudaStreamNonBlocking);
        cudaStreamCreateWithFlags(&s2, cudaStreamNonBlocking);
        cudaEventCreateWithFlags(&evSetup, cudaEventDisableTiming);
        cudaEventCreateWithFlags(&evCSR, cudaEventDisableTiming);
        cudaEventCreateWithFlags(&evA, cudaEventDisableTiming);
        cudaEventCreateWithFlags(&evRes1, cudaEventDisableTiming);
        cudaEventCreateWithFlags(&evX2, cudaEventDisableTiming);
        cudaEventCreateWithFlags(&evRes2, cudaEventDisableTiming);
        cudaEventCreateWithFlags(&evX3, cudaEventDisableTiming);
        cudaEventCreateWithFlags(&evRes3, cudaEventDisableTiming);
    }

    dim3 mma_grid(2, (N + 127) / 128);
    dim3 mma_grid64(1, (N + 127) / 128);
    dim3 gemm_grid_64(1, (N + BM - 1) / BM);
    int bn_blocks = (N + 255) / 256;
    int sc_blocks = (N + 255) / 256;
    long long tot256 = (long long)N * 256;
    const int SLOT = 256 * 768;

    // ---- setup + fork ----
    k_init<<<gb(N, 256), 256>>>(N);
    cudaEventRecord(evSetup, 0);
    cudaStreamWaitEvent(s1, evSetup, 0);
    cudaStreamWaitEvent(s2, evSetup, 0);

    // s1: CSR build (3-phase scan) + fused layer4 weights
    k_hist<<<gb(E, 256), 256, 0, s1>>>(ei, E);
    k_dinv<<<gb(N, 256), 256, 0, s1>>>(N);
    k_scan1<<<sc_blocks, 256, 0, s1>>>(N);
    k_scan2<<<1, 256, 0, s1>>>(sc_blocks, N);
    k_scan3<<<gb(N, 256), 256, 0, s1>>>(N);
    k_fill<<<gb(E, 256), 256, 0, s1>>>(ei, E);
    k_w4comb<<<17, 64, 0, s1>>>(W4, pW, b4, pb);
    cudaEventRecord(evCSR, s1);

    // s2: residual-path weight splits
    k_buildB<<<256, 256, 0, s2>>>(r1W, Bt2 + 1 * SLOT);
    k_buildB<<<256, 256, 0, s2>>>(Wg, Bt2 + 2 * SLOT);
    k_buildB64<<<128, 256, 0, s2>>>(r2W, Bt2 + 3 * SLOT);

    // s0: main-path splits + h1
    k_buildB<<<256, 256>>>(W1, Bt2 + 0 * SLOT);
    k_buildA<<<gb(tot256, 256), 256>>>(x, A2, tot256);
    cudaEventRecord(evA, 0);

    cudaStreamWaitEvent(s2, evA, 0);
    k_mma_gemm<<<mma_grid, 256, 0, s2>>>(A2, Bt2 + 1 * SLOT, r1b, P3, nullptr, N, 256);  // res1
    cudaEventRecord(evRes1, s2);

    k_mma_gemm<<<mma_grid, 256>>>(A2, Bt2 + 0 * SLOT, nullptr, nullptr, H16, N, 256);    // h1 fp16

    // ---- layer 1 ----
    cudaStreamWaitEvent(0, evCSR, 0);
    k_gcn_gather_h<<<gb((long long)N * 32, 256), 256>>>(H16, b1, P1, N);
    k_bn_stats<<<bn_blocks, 256>>>(P1, bnsum + 0, bnsq + 0, N, 256);
    k_bn_finalize<<<1, 256>>>(g1, be1, bnsum + 0, bnsq + 0, bnscale + 0, bnshift + 0, invn, 256);
    cudaStreamWaitEvent(0, evRes1, 0);
    k_bn_apply_add_split<<<gb(tot256, 256), 256>>>(P1, P3, bnscale + 0, bnshift + 0, A2, tot256);
    cudaEventRecord(evX2, 0);

    // ---- layer 2 ----
    cudaStreamWaitEvent(s2, evX2, 0);
    k_mma_gemm<<<mma_grid64, 256, 0, s2>>>(A2, Bt2 + 3 * SLOT, r2b, P1, nullptr, N, 64);  // res2
    cudaEventRecord(evRes2, s2);

    k_mma_gemm<<<mma_grid, 256>>>(A2, Bt2 + 2 * SLOT, nullptr, nullptr, H16, N, 256);     // h2 fp16
    k_gat_logits<<<gb((long long)N * 32, 256), 256>>>(H16, a_s, a_d, N);
    k_gat_gather<<<gb((long long)N * 32, 256), 256>>>(H16, bg, P3, N);                    // out2pre
    k_bn_stats<<<bn_blocks, 64>>>(P3, bnsum + 256, bnsq + 256, N, 64);
    k_bn_finalize<<<1, 64>>>(g2, be2, bnsum + 256, bnsq + 256, bnscale + 256, bnshift + 256, invn, 64);
    cudaStreamWaitEvent(0, evRes2, 0);
    k_bn_apply_add<<<gb((long long)N * 64, 256), 256>>>(P3, P1, bnscale + 256, bnshift + 256,
                                                        P0, (long long)N * 64, 64);  // x3
    cudaEventRecord(evX3, 0);

    // ---- layer 3 ----
    cudaStreamWaitEvent(s2, evX3, 0);
    k_sgemm<<<gemm_grid_64, 256, 0, s2>>>(P0, r3W, r3b, P2, N, 64, 16);          // res3
    cudaEventRecord(evRes3, s2);

    k_sgemm<<<gemm_grid_64, 256>>>(P0, W3, nullptr, P3, N, 64, 16);              // h3
    k_gcn_gather<16><<<gb((long long)N * 4, 256), 256>>>(P3, b3, P1, N);
    k_bn_stats<<<bn_blocks, 16>>>(P1, bnsum + 320, bnsq + 320, N, 16);
    k_bn_finalize<<<1, 32>>>(g3, be3, bnsum + 320, bnsq + 320, bnscale + 320, bnshift + 320, invn, 16);
    cudaStreamWaitEvent(0, evRes3, 0);
    k_bn_apply_add<<<gb((long long)N * 16, 256), 256>>>(P1, P2, bnscale + 320, bnshift + 320,
                                                        P3, (long long)N * 16, 16);  // x4

    // ---- layer 4 + final projection (fused: (A_hat x4) @ W4p + b4p) ----
    k_gcn_gather<16><<<gb((long long)N * 4, 256), 256>>>(P3, nullptr, P0, N);
    k_sgemm<<<gemm_grid_64, 256>>>(P0, W4p, b4p, out, N, 16, 64);
}

// round 15
// speedup vs baseline: 1.4011x; 1.4011x over previous
#include <cuda_runtime.h>
#include <cuda_bf16.h>
#include <cstdint>

// ---------------------------------------------------------------------------
// GCNModel: GCN(256)+BN+LReLU+res -> GAT(4x64,mean)+BN+LReLU+res ->
//           GCN(64->16)+BN+LReLU+res -> GCN(16->64) -> Linear(64->64)
// N=50000, E=800000. edge_index int32.
// Big GEMMs + res2: mma.sync bf16 hi/lo split (K_eff=768), staged A2.
// Graph aggregation: CSR-by-dst per-node warp gather (fp32, no atomics), x2.
// GAT softmax: unshifted exp. Layer4+proj fused. 3-phase parallel scan.
// Stream fork-join: CSR build, res1/res2/res3 GEMMs overlap the main chain.
// ---------------------------------------------------------------------------

typedef int eidx_t;

#define NMAX 50000
#define EMAX 800000

__device__ __align__(16) float g_P0[NMAX * 256];
__device__ __align__(16) float g_P1[NMAX * 256];
__device__ __align__(16) float g_P2[NMAX * 256];
__device__ __align__(16) float g_P3[NMAX * 256];
__device__ float g_dinv[NMAX];
__device__ int   g_degi[NMAX];
__device__ int   g_csr_ptr[NMAX + 1];
__device__ int   g_csr_cnt[NMAX];
__device__ int   g_csr_src[EMAX];
__device__ int   g_blocksum[256];
__device__ int   g_bloff[256];
__device__ __align__(16) float g_als[NMAX * 4];
__device__ __align__(16) float g_ald[NMAX * 4];
__device__ __align__(16) float g_eself[NMAX * 4];
__device__ float g_bnsum[512];
__device__ float g_bnsq[512];
__device__ float g_bnscale[512];
__device__ float g_bnshift[512];
__device__ __align__(16) float g_W4p[16 * 64];
__device__ __align__(16) float g_b4p[64];

// bf16 split operands ([hi|hi|lo] for A, [hi|lo|hi] for B^T; slot3 = r2W padded)
__device__ __align__(16) __nv_bfloat16 g_A2[(size_t)50048 * 768];
__device__ __align__(16) __nv_bfloat16 g_Bt2[4][256 * 768];

// ---- helpers --------------------------------------------------------------

__device__ __forceinline__ float lrelu2(float x) { return x > 0.f ? x : 0.2f * x; }

__device__ __forceinline__ void ldsm4(uint32_t* r, uint32_t addr) {
    asm volatile("ldmatrix.sync.aligned.m8n8.x4.shared.b16 {%0,%1,%2,%3}, [%4];"
                 : "=r"(r[0]), "=r"(r[1]), "=r"(r[2]), "=r"(r[3]) : "r"(addr));
}

__device__ __forceinline__ void mma16816(float* c, const uint32_t* a,
                                         uint32_t b0, uint32_t b1) {
    asm volatile(
        "mma.sync.aligned.m16n8k16.row.col.f32.bf16.bf16.f32 "
        "{%0,%1,%2,%3}, {%4,%5,%6,%7}, {%8,%9}, {%0,%1,%2,%3};"
        : "+f"(c[0]), "+f"(c[1]), "+f"(c[2]), "+f"(c[3])
        : "r"(a[0]), "r"(a[1]), "r"(a[2]), "r"(a[3]), "r"(b0), "r"(b1));
}

// ---- init: zero degree/csr counters + all BN accumulators -----------------

__global__ void k_init(int n) {
    int i = blockIdx.x * blockDim.x + threadIdx.x;
    if (i < n) { g_degi[i] = 0; g_csr_cnt[i] = 0; }
    if (i < 512) { g_bnsum[i] = 0.f; g_bnsq[i] = 0.f; }
}

// ---- CSR build ------------------------------------------------------------

__global__ void k_hist(const eidx_t* __restrict__ ei, int E) {
    int e = blockIdx.x * blockDim.x + threadIdx.x;
    if (e < E) atomicAdd(&g_degi[(int)ei[E + e]], 1);
}

__global__ void k_dinv(int n) {
    int i = blockIdx.x * blockDim.x + threadIdx.x;
    if (i < n) g_dinv[i] = rsqrtf((float)g_degi[i] + 1.0f);
}

// 3-phase scan: per-block excl scan -> scan block sums -> add offsets
__global__ void k_scan1(int n) {
    __shared__ int sh[256];
    int tid = threadIdx.x;
    int i = blockIdx.x * 256 + tid;
    int v = (i < n) ? g_degi[i] : 0;
    sh[tid] = v;
    __syncthreads();
#pragma unroll
    for (int off = 1; off < 256; off <<= 1) {
        int t = (tid >= off) ? sh[tid - off] : 0;
        __syncthreads();
        sh[tid] += t;
        __syncthreads();
    }
    if (i < n) g_csr_ptr[i] = sh[tid] - v;   // exclusive
    if (tid == 255) g_blocksum[blockIdx.x] = sh[255];
}

__global__ void k_scan2(int nb, int n) {
    __shared__ int sh[256];
    int tid = threadIdx.x;
    int v = (tid < nb) ? g_blocksum[tid] : 0;
    sh[tid] = v;
    __syncthreads();
#pragma unroll
    for (int off = 1; off < 256; off <<= 1) {
        int t = (tid >= off) ? sh[tid - off] : 0;
        __syncthreads();
        sh[tid] += t;
        __syncthreads();
    }
    g_bloff[tid] = sh[tid] - v;              // exclusive
    if (tid == nb - 1) g_csr_ptr[n] = sh[tid];
}

__global__ void k_scan3(int n) {
    int i = blockIdx.x * blockDim.x + threadIdx.x;
    if (i < n) g_csr_ptr[i] += g_bloff[i >> 8];
}

__global__ void k_fill(const eidx_t* __restrict__ ei, int E) {
    int e = blockIdx.x * blockDim.x + threadIdx.x;
    if (e >= E) return;
    int dst = (int)ei[E + e];
    int pos = g_csr_ptr[dst] + atomicAdd(&g_csr_cnt[dst], 1);
    g_csr_src[pos] = (int)ei[e];
}

// ---- fused layer4 weights: W4p = W4 @ pW ; b4p = b4 @ pW + pb -------------

__global__ void k_w4comb(const float* __restrict__ W4, const float* __restrict__ pW,
                         const float* __restrict__ b4, const float* __restrict__ pb) {
    int m = threadIdx.x;   // 64
    int k = blockIdx.x;    // 0..16
    if (k < 16) {
        float s = 0.f;
        for (int j = 0; j < 64; j++) s += W4[k * 64 + j] * pW[j * 64 + m];
        g_W4p[k * 64 + m] = s;
    } else {
        float s = pb[m];
        for (int j = 0; j < 64; j++) s += b4[j] * pW[j * 64 + m];
        g_b4p[m] = s;
    }
}

// ---- split builders -------------------------------------------------------

__global__ void k_buildA(const float* __restrict__ X, __nv_bfloat16* __restrict__ A2,
                         long long total) {
    long long i = (long long)blockIdx.x * blockDim.x + threadIdx.x;
    if (i >= total) return;
    int r = (int)(i >> 8), k = (int)(i & 255);
    float v = X[i];
    __nv_bfloat16 h = __float2bfloat16(v);
    __nv_bfloat16 l = __float2bfloat16(v - __bfloat162float(h));
    size_t b = (size_t)r * 768 + k;
    A2[b] = h;
    A2[b + 256] = h;
    A2[b + 512] = l;
}

__global__ void k_buildB(const float* __restrict__ W, __nv_bfloat16* __restrict__ Bt) {
    int idx = blockIdx.x * blockDim.x + threadIdx.x;  // 65536
    int m = idx >> 8, k = idx & 255;
    float v = W[k * 256 + m];
    __nv_bfloat16 h = __float2bfloat16(v);
    __nv_bfloat16 l = __float2bfloat16(v - __bfloat162float(h));
    size_t b = (size_t)m * 768 + k;
    Bt[b] = h;
    Bt[b + 256] = l;
    Bt[b + 512] = h;
}

__global__ void k_buildB64(const float* __restrict__ W, __nv_bfloat16* __restrict__ Bt) {
    int idx = blockIdx.x * blockDim.x + threadIdx.x;  // 32768
    int m = idx >> 8, k = idx & 255;
    float v = (m < 64) ? W[k * 64 + m] : 0.0f;
    __nv_bfloat16 h = __float2bfloat16(v);
    __nv_bfloat16 l = __float2bfloat16(v - __bfloat162float(h));
    size_t b = (size_t)m * 768 + k;
    Bt[b] = h;
    Bt[b + 256] = l;
    Bt[b + 512] = h;
}

// ---- mma.sync bf16 GEMM: C[n,M] = A2[n,768] @ Bt2[.,768]^T (+bias) --------

#define MSTRIDE 80
#define MTILEB (128 * MSTRIDE)

__global__ __launch_bounds__(256)
void k_mma_gemm(const __nv_bfloat16* __restrict__ A2, const __nv_bfloat16* __restrict__ Bt2,
                const float* __restrict__ bias, float* __restrict__ C, int n, int M) {
    __shared__ __align__(16) unsigned char As[2][MTILEB];
    __shared__ __align__(16) unsigned char Bs[2][MTILEB];

    int tid = threadIdx.x, lane = tid & 31, warp = tid >> 5;
    int wm = warp & 1, wn = warp >> 1;
    int row0 = blockIdx.y * 128, col0 = blockIdx.x * 128;

    int v0 = tid * 2, v1 = v0 + 1;
    int ar0 = v0 >> 2, ac0 = v0 & 3;
    int ar1 = v1 >> 2, ac1 = v1 & 3;
    int rA0 = row0 + ar0; rA0 = rA0 < n ? rA0 : n - 1;
    int rA1 = row0 + ar1; rA1 = rA1 < n ? rA1 : n - 1;
    const __nv_bfloat16* pA0 = A2 + (size_t)rA0 * 768 + ac0 * 8;
    const __nv_bfloat16* pA1 = A2 + (size_t)rA1 * 768 + ac1 * 8;
    const __nv_bfloat16* pB0 = Bt2 + (size_t)(col0 + ar0) * 768 + ac0 * 8;
    const __nv_bfloat16* pB1 = Bt2 + (size_t)(col0 + ar1) * 768 + ac1 * 8;

    uint32_t asb = (uint32_t)__cvta_generic_to_shared(As);
    uint32_t bsb = (uint32_t)__cvta_generic_to_shared(Bs);

    float acc[4][4][4];
#pragma unroll
    for (int t = 0; t < 4; t++)
#pragma unroll
        for (int j = 0; j < 4; j++)
#pragma unroll
            for (int q = 0; q < 4; q++) acc[t][j][q] = 0.0f;

    const int KT = 24;
    uint4 ra0, ra1, rb0, rb1;

    ra0 = *(const uint4*)pA0;
    ra1 = *(const uint4*)pA1;
    rb0 = *(const uint4*)pB0;
    rb1 = *(const uint4*)pB1;
    *(uint4*)(As[0] + ar0 * MSTRIDE + ac0 * 16) = ra0;
    *(uint4*)(As[0] + ar1 * MSTRIDE + ac1 * 16) = ra1;
    *(uint4*)(Bs[0] + ar0 * MSTRIDE + ac0 * 16) = rb0;
    *(uint4*)(Bs[0] + ar1 * MSTRIDE + ac1 * 16) = rb1;
    __syncthreads();

    for (int kt = 0; kt < KT; kt++) {
        int buf = kt & 1;
        if (kt + 1 < KT) {
            int off = (kt + 1) * 32;
            ra0 = *(const uint4*)(pA0 + off);
            ra1 = *(const uint4*)(pA1 + off);
            rb0 = *(const uint4*)(pB0 + off);
            rb1 = *(const uint4*)(pB1 + off);
        }
        uint32_t ab = asb + buf * MTILEB;
        uint32_t bb = bsb + buf * MTILEB;
#pragma unroll
        for (int s = 0; s < 2; s++) {
            uint32_t a[4][4];
            uint32_t br[2][4];
#pragma unroll
            for (int t = 0; t < 4; t++) {
                uint32_t ad = ab + (uint32_t)((wm * 64 + t * 16 + (lane & 15)) * MSTRIDE +
                                              (s * 16 + (lane >> 4) * 8) * 2);
                ldsm4(a[t], ad);
            }
#pragma unroll
            for (int p = 0; p < 2; p++) {
                uint32_t bd = bb + (uint32_t)((wn * 32 + p * 16 + (lane & 7) + (lane >> 4) * 8) * MSTRIDE +
                                              (s * 16 + ((lane >> 3) & 1) * 8) * 2);
                ldsm4(br[p], bd);
            }
#pragma unroll
            for (int t = 0; t < 4; t++)
#pragma unroll
                for (int j = 0; j < 4; j++)
                    mma16816(acc[t][j], a[t], br[j >> 1][(j & 1) * 2],
                             br[j >> 1][(j & 1) * 2 + 1]);
        }
        if (kt + 1 < KT) {
            int nb = (kt + 1) & 1;
            *(uint4*)(As[nb] + ar0 * MSTRIDE + ac0 * 16) = ra0;
            *(uint4*)(As[nb] + ar1 * MSTRIDE + ac1 * 16) = ra1;
            *(uint4*)(Bs[nb] + ar0 * MSTRIDE + ac0 * 16) = rb0;
            *(uint4*)(Bs[nb] + ar1 * MSTRIDE + ac1 * 16) = rb1;
        }
        __syncthreads();
    }

#pragma unroll
    for (int t = 0; t < 4; t++) {
        int r1 = row0 + wm * 64 + t * 16 + (lane >> 2);
        int r2 = r1 + 8;
#pragma unroll
        for (int j = 0; j < 4; j++) {
            int c = col0 + wn * 32 + j * 8 + (lane & 3) * 2;
            if (c >= M) continue;
            float bx = bias ? bias[c] : 0.f;
            float by = bias ? bias[c + 1] : 0.f;
            if (r1 < n) {
                float2 v = make_float2(acc[t][j][0] + bx, acc[t][j][1] + by);
                *(float2*)(C + (size_t)r1 * M + c) = v;
            }
            if (r2 < n) {
                float2 v = make_float2(acc[t][j][2] + bx, acc[t][j][3] + by);
                *(float2*)(C + (size_t)r2 * M + c) = v;
            }
        }
    }
}

// ---- small SGEMM (64x64 tile) for M<=64 outputs ---------------------------

#define BM 64
#define BN 64
#define BKK 16

__global__ void k_sgemm(const float* __restrict__ A, const float* __restrict__ B,
                        const float* __restrict__ bias, float* __restrict__ C,
                        int n, int K, int M) {
    __shared__ __align__(16) float As[BKK][BM];
    __shared__ __align__(16) float Bs[BKK][BN];
    int tid = threadIdx.x;
    int tx = tid & 15, ty = tid >> 4;
    int row0 = blockIdx.y * BM;
    int col0 = blockIdx.x * BN;
    int ar = tid >> 2, ak4 = (tid & 3) * 4;
    int bk = tid >> 4, bc = (tid & 15) * 4;

    float acc[4][4];
#pragma unroll
    for (int i = 0; i < 4; i++)
#pragma unroll
        for (int j = 0; j < 4; j++) acc[i][j] = 0.0f;

    for (int k0 = 0; k0 < K; k0 += BKK) {
        float4 av = make_float4(0.f, 0.f, 0.f, 0.f);
        if (row0 + ar < n)
            av = *(const float4*)(A + (long long)(row0 + ar) * K + k0 + ak4);
        As[ak4 + 0][ar] = av.x;
        As[ak4 + 1][ar] = av.y;
        As[ak4 + 2][ar] = av.z;
        As[ak4 + 3][ar] = av.w;

        float4 bv = make_float4(0.f, 0.f, 0.f, 0.f);
        if (col0 + bc < M)
            bv = *(const float4*)(B + (long long)(k0 + bk) * M + col0 + bc);
        *(float4*)&Bs[bk][bc] = bv;

        __syncthreads();
#pragma unroll
        for (int k = 0; k < BKK; k++) {
            float4 a4 = *(const float4*)&As[k][ty * 4];
            float4 b4 = *(const float4*)&Bs[k][tx * 4];
            float ar_[4] = {a4.x, a4.y, a4.z, a4.w};
            float br_[4] = {b4.x, b4.y, b4.z, b4.w};
#pragma unroll
            for (int i = 0; i < 4; i++)
#pragma unroll
                for (int j = 0; j < 4; j++)
                    acc[i][j] = fmaf(ar_[i], br_[j], acc[i][j]);
        }
        __syncthreads();
    }

#pragma unroll
    for (int i = 0; i < 4; i++) {
        int r = row0 + ty * 4 + i;
        if (r >= n) continue;
#pragma unroll
        for (int j = 0; j < 4; j++) {
            int c = col0 + tx * 4 + j;
            if (c < M) {
                float bv = bias ? bias[c] : 0.0f;
                C[(long long)r * M + c] = acc[i][j] + bv;
            }
        }
    }
}

// ---- GCN gather (edge loop unrolled x2; bias nullable) --------------------

template <int D>
__global__ void k_gcn_gather(const float* __restrict__ H, const float* __restrict__ b,
                             float* __restrict__ OUT, int n) {
    constexpr int L4 = D / 4;
    constexpr int T4 = (L4 < 32) ? L4 : 32;
    constexpr int V4 = L4 / T4;
    long long gt = (long long)blockIdx.x * blockDim.x + threadIdx.x;
    int node = (int)(gt / T4);
    int sub = (int)(gt % T4);
    if (node >= n) return;
    float dv = g_dinv[node];
    float self = dv * dv;
    const float4* hn = (const float4*)(H + (size_t)node * D);
    const float4* bb = (const float4*)b;
    float4 acc[V4];
#pragma unroll
    for (int v = 0; v < V4; v++) {
        int idx = sub + v * T4;
        float4 h = hn[idx];
        float4 bv = b ? bb[idx] : make_float4(0.f, 0.f, 0.f, 0.f);
        acc[v] = make_float4(h.x * self + bv.x, h.y * self + bv.y,
                             h.z * self + bv.z, h.w * self + bv.w);
    }
    int beg = g_csr_ptr[node], end = g_csr_ptr[node + 1];
    int p = beg;
    for (; p + 2 <= end; p += 2) {
        int s0 = g_csr_src[p];
        int s1 = g_csr_src[p + 1];
        float n0 = g_dinv[s0] * dv;
        float n1 = g_dinv[s1] * dv;
        const float4* h0 = (const float4*)(H + (size_t)s0 * D);
        const float4* h1 = (const float4*)(H + (size_t)s1 * D);
#pragma unroll
        for (int v = 0; v < V4; v++) {
            float4 a = h0[sub + v * T4];
            float4 c = h1[sub + v * T4];
            acc[v].x = fmaf(a.x, n0, acc[v].x);
            acc[v].y = fmaf(a.y, n0, acc[v].y);
            acc[v].z = fmaf(a.z, n0, acc[v].z);
            acc[v].w = fmaf(a.w, n0, acc[v].w);
            acc[v].x = fmaf(c.x, n1, acc[v].x);
            acc[v].y = fmaf(c.y, n1, acc[v].y);
            acc[v].z = fmaf(c.z, n1, acc[v].z);
            acc[v].w = fmaf(c.w, n1, acc[v].w);
        }
    }
    if (p < end) {
        int s0 = g_csr_src[p];
        float n0 = g_dinv[s0] * dv;
        const float4* h0 = (const float4*)(H + (size_t)s0 * D);
#pragma unroll
        for (int v = 0; v < V4; v++) {
            float4 a = h0[sub + v * T4];
            acc[v].x = fmaf(a.x, n0, acc[v].x);
            acc[v].y = fmaf(a.y, n0, acc[v].y);
            acc[v].z = fmaf(a.z, n0, acc[v].z);
            acc[v].w = fmaf(a.w, n0, acc[v].w);
        }
    }
    float4* op = (float4*)(OUT + (size_t)node * D);
#pragma unroll
    for (int v = 0; v < V4; v++) op[sub + v * T4] = acc[v];
}

// ---- BatchNorm (pointer-parameterized) ------------------------------------

__global__ void k_bn_stats(const float* __restrict__ X, float* __restrict__ bnsum,
                           float* __restrict__ bnsq, int n, int C) {
    int c = threadIdx.x;
    long long r0 = (long long)blockIdx.x * 256;
    long long r1 = r0 + 256;
    if (r1 > n) r1 = n;
    float s = 0.f, q = 0.f;
    for (long long r = r0; r < r1; r++) {
        float v = X[r * C + c];
        s += v;
        q += v * v;
    }
    atomicAdd(&bnsum[c], s);
    atomicAdd(&bnsq[c], q);
}

__global__ void k_bn_finalize(const float* __restrict__ g, const float* __restrict__ be,
                              const float* __restrict__ bnsum, const float* __restrict__ bnsq,
                              float* __restrict__ scale, float* __restrict__ shift,
                              float invn, int C) {
    int c = blockIdx.x * blockDim.x + threadIdx.x;
    if (c >= C) return;
    float mean = bnsum[c] * invn;
    float var = bnsq[c] * invn - mean * mean;
    float r = rsqrtf(var + 1e-5f);
    float sc = g[c] * r;
    scale[c] = sc;
    shift[c] = be[c] - mean * sc;
}

__global__ void k_bn_apply_add(const float* __restrict__ X, const float* __restrict__ R,
                               const float* __restrict__ scale, const float* __restrict__ shift,
                               float* __restrict__ OUT, long long total, int C) {
    long long i = (long long)blockIdx.x * blockDim.x + threadIdx.x;
    if (i >= total) return;
    int c = (int)(i % C);
    float v = fmaf(X[i], scale[c], shift[c]);
    v = v > 0.f ? v : 0.01f * v;
    OUT[i] = v + R[i];
}

// layer-1 epilogue: x2 only needed as bf16 split -> write A2 only
__global__ void k_bn_apply_add_split(const float* __restrict__ X, const float* __restrict__ R,
                                     const float* __restrict__ scale, const float* __restrict__ shift,
                                     __nv_bfloat16* __restrict__ A2, long long total) {
    long long i = (long long)blockIdx.x * blockDim.x + threadIdx.x;
    if (i >= total) return;
    int c = (int)(i & 255);
    int r = (int)(i >> 8);
    float v = fmaf(X[i], scale[c], shift[c]);
    v = v > 0.f ? v : 0.01f * v;
    v += R[i];
    __nv_bfloat16 h = __float2bfloat16(v);
    __nv_bfloat16 l = __float2bfloat16(v - __bfloat162float(h));
    size_t b = (size_t)r * 768 + c;
    A2[b] = h;
    A2[b + 256] = h;
    A2[b + 512] = l;
}

// ---- GAT ------------------------------------------------------------------

__global__ void k_gat_logits(const float* __restrict__ H2, const float* __restrict__ a_s,
                             const float* __restrict__ a_d, int n) {
    __shared__ float sa[256], sd[256];
    sa[threadIdx.x] = a_s[threadIdx.x];
    sd[threadIdx.x] = a_d[threadIdx.x];
    __syncthreads();
    int gw = (int)(((long long)blockIdx.x * blockDim.x + threadIdx.x) >> 5);
    int lane = threadIdx.x & 31;
    if (gw >= n) return;
    const float4* hp = (const float4*)(H2 + (long long)gw * 256);
    float4 h0 = hp[lane * 2];
    float4 h1 = hp[lane * 2 + 1];
    int base = lane * 8;
    float ps = h0.x * sa[base + 0] + h0.y * sa[base + 1] + h0.z * sa[base + 2] +
               h0.w * sa[base + 3] + h1.x * sa[base + 4] + h1.y * sa[base + 5] +
               h1.z * sa[base + 6] + h1.w * sa[base + 7];
    float pd = h0.x * sd[base + 0] + h0.y * sd[base + 1] + h0.z * sd[base + 2] +
               h0.w * sd[base + 3] + h1.x * sd[base + 4] + h1.y * sd[base + 5] +
               h1.z * sd[base + 6] + h1.w * sd[base + 7];
#pragma unroll
    for (int off = 4; off; off >>= 1) {
        ps += __shfl_down_sync(0xffffffffu, ps, off);
        pd += __shfl_down_sync(0xffffffffu, pd, off);
    }
    if ((lane & 7) == 0) {
        int h = lane >> 3;
        g_als[gw * 4 + h] = ps;
        g_ald[gw * 4 + h] = pd;
        g_eself[gw * 4 + h] = lrelu2(ps + pd);
    }
}

__global__ void k_gat_gather(const float* __restrict__ H2, const float* __restrict__ bg,
                             float* __restrict__ OUT, int n) {
    long long gt = (long long)blockIdx.x * blockDim.x + threadIdx.x;
    int node = (int)(gt >> 5);
    int lane = threadIdx.x & 31;
    if (node >= n) return;
    int h = lane >> 3;
    int beg = g_csr_ptr[node], end = g_csr_ptr[node + 1];

    float ald_h = 0.f, es = 0.f, denom = 0.f;
    if (lane < 4) {
        ald_h = g_ald[node * 4 + lane];
        es = expf(g_eself[node * 4 + lane]);
        denom = es;
    }
    float w0 = __shfl_sync(0xffffffffu, es, h);

    const float4* hn = (const float4*)(H2 + (size_t)node * 256);
    float4 a0 = hn[lane * 2], a1 = hn[lane * 2 + 1];
    float acc[8] = {a0.x * w0, a0.y * w0, a0.z * w0, a0.w * w0,
                    a1.x * w0, a1.y * w0, a1.z * w0, a1.w * w0};

    int p = beg;
    for (; p + 2 <= end; p += 2) {
        int s0 = g_csr_src[p];
        int s1 = g_csr_src[p + 1];
        float e0 = 0.f, e1 = 0.f;
        if (lane < 4) {
            e0 = expf(lrelu2(g_als[s0 * 4 + lane] + ald_h));
            e1 = expf(lrelu2(g_als[s1 * 4 + lane] + ald_h));
            denom += e0 + e1;
        }
        float wa = __shfl_sync(0xffffffffu, e0, h);
        float wb = __shfl_sync(0xffffffffu, e1, h);
        const float4* ha = (const float4*)(H2 + (size_t)s0 * 256);
        const float4* hb = (const float4*)(H2 + (size_t)s1 * 256);
        float4 x0 = ha[lane * 2], x1 = ha[lane * 2 + 1];
        float4 y0 = hb[lane * 2], y1 = hb[lane * 2 + 1];
        acc[0] = fmaf(x0.x, wa, acc[0]); acc[0] = fmaf(y0.x, wb, acc[0]);
        acc[1] = fmaf(x0.y, wa, acc[1]); acc[1] = fmaf(y0.y, wb, acc[1]);
        acc[2] = fmaf(x0.z, wa, acc[2]); acc[2] = fmaf(y0.z, wb, acc[2]);
        acc[3] = fmaf(x0.w, wa, acc[3]); acc[3] = fmaf(y0.w, wb, acc[3]);
        acc[4] = fmaf(x1.x, wa, acc[4]); acc[4] = fmaf(y1.x, wb, acc[4]);
        acc[5] = fmaf(x1.y, wa, acc[5]); acc[5] = fmaf(y1.y, wb, acc[5]);
        acc[6] = fmaf(x1.z, wa, acc[6]); acc[6] = fmaf(y1.z, wb, acc[6]);
        acc[7] = fmaf(x1.w, wa, acc[7]); acc[7] = fmaf(y1.w, wb, acc[7]);
    }
    if (p < end) {
        int s0 = g_csr_src[p];
        float e0 = 0.f;
        if (lane < 4) {
            e0 = expf(lrelu2(g_als[s0 * 4 + lane] + ald_h));
            denom += e0;
        }
        float wa = __shfl_sync(0xffffffffu, e0, h);
        const float4* ha = (const float4*)(H2 + (size_t)s0 * 256);
        float4 x0 = ha[lane * 2], x1 = ha[lane * 2 + 1];
        acc[0] = fmaf(x0.x, wa, acc[0]);
        acc[1] = fmaf(x0.y, wa, acc[1]);
        acc[2] = fmaf(x0.z, wa, acc[2]);
        acc[3] = fmaf(x0.w, wa, acc[3]);
        acc[4] = fmaf(x1.x, wa, acc[4]);
        acc[5] = fmaf(x1.y, wa, acc[5]);
        acc[6] = fmaf(x1.z, wa, acc[6]);
        acc[7] = fmaf(x1.w, wa, acc[7]);
    }

    float dh = __shfl_sync(0xffffffffu, denom, h);
    float inv = 1.0f / dh;
    float v[8];
#pragma unroll
    for (int j = 0; j < 8; j++) {
        v[j] = acc[j] * inv;
        v[j] += __shfl_xor_sync(0xffffffffu, v[j], 8);
        v[j] += __shfl_xor_sync(0xffffffffu, v[j], 16);
    }
    if (lane < 8) {
        int d0 = lane * 8;
        float4 o0 = make_float4(0.25f * v[0] + bg[d0 + 0], 0.25f * v[1] + bg[d0 + 1],
                                0.25f * v[2] + bg[d0 + 2], 0.25f * v[3] + bg[d0 + 3]);
        float4 o1 = make_float4(0.25f * v[4] + bg[d0 + 4], 0.25f * v[5] + bg[d0 + 5],
                                0.25f * v[6] + bg[d0 + 6], 0.25f * v[7] + bg[d0 + 7]);
        float4* op = (float4*)(OUT + (size_t)node * 64 + d0);
        op[0] = o0;
        op[1] = o1;
    }
}

// ---------------------------------------------------------------------------
// host
// ---------------------------------------------------------------------------

static inline unsigned gb(long long total, int block) {
    return (unsigned)((total + block - 1) / block);
}

extern "C" void kernel_launch(void* const* d_in, const int* in_sizes, int n_in,
                              void* d_out, int out_size) {
    const float* x    = (const float*)d_in[0];
    const eidx_t* ei  = (const eidx_t*)d_in[1];
    const float* W1   = (const float*)d_in[2];
    const float* b1   = (const float*)d_in[3];
    const float* g1   = (const float*)d_in[4];
    const float* be1  = (const float*)d_in[5];
    const float* Wg   = (const float*)d_in[6];
    const float* a_s  = (const float*)d_in[7];
    const float* a_d  = (const float*)d_in[8];
    const float* bg   = (const float*)d_in[9];
    const float* g2   = (const float*)d_in[10];
    const float* be2  = (const float*)d_in[11];
    const float* W3   = (const float*)d_in[12];
    const float* b3   = (const float*)d_in[13];
    const float* g3   = (const float*)d_in[14];
    const float* be3  = (const float*)d_in[15];
    const float* W4   = (const float*)d_in[16];
    const float* b4   = (const float*)d_in[17];
    const float* r1W  = (const float*)d_in[18];
    const float* r1b  = (const float*)d_in[19];
    const float* r2W  = (const float*)d_in[20];
    const float* r2b  = (const float*)d_in[21];
    const float* r3W  = (const float*)d_in[22];
    const float* r3b  = (const float*)d_in[23];
    const float* pW   = (const float*)d_in[24];
    const float* pb   = (const float*)d_in[25];
    float* out = (float*)d_out;

    int N = in_sizes[0] / 256;
    int E = in_sizes[1] / 2;
    float invn = 1.0f / (float)N;

    float *P0, *P1, *P2, *P3, *bnsum, *bnsq, *bnscale, *bnshift, *W4p, *b4p;
    __nv_bfloat16 *A2, *Bt2;
    cudaGetSymbolAddress((void**)&P0, g_P0);
    cudaGetSymbolAddress((void**)&P1, g_P1);
    cudaGetSymbolAddress((void**)&P2, g_P2);
    cudaGetSymbolAddress((void**)&P3, g_P3);
    cudaGetSymbolAddress((void**)&bnsum, g_bnsum);
    cudaGetSymbolAddress((void**)&bnsq, g_bnsq);
    cudaGetSymbolAddress((void**)&bnscale, g_bnscale);
    cudaGetSymbolAddress((void**)&bnshift, g_bnshift);
    cudaGetSymbolAddress((void**)&W4p, g_W4p);
    cudaGetSymbolAddress((void**)&b4p, g_b4p);
    cudaGetSymbolAddress((void**)&A2, g_A2);
    cudaGetSymbolAddress((void**)&Bt2, g_Bt2);

    static cudaStream_t s1 = nullptr, s2 = nullptr;
    static cudaEvent_t evSetup, evCSR, evA, evRes1, evX2, evRes2, evX3, evRes3;
    if (!s1) {
        cudaStreamCreateWithFlags(&s1, cudaStreamNonBlocking);
        cudaStreamCreateWithFlags(&s2, cudaStreamNonBlocking);
        cudaEventCreateWithFlags(&evSetup, cudaEventDisableTiming);
        cudaEventCreateWithFlags(&evCSR, cudaEventDisableTiming);
        cudaEventCreateWithFlags(&evA, cudaEventDisableTiming);
        cudaEventCreateWithFlags(&evRes1, cudaEventDisableTiming);
        cudaEventCreateWithFlags(&evX2, cudaEventDisableTiming);
        cudaEventCreateWithFlags(&evRes2, cudaEventDisableTiming);
        cudaEventCreateWithFlags(&evX3, cudaEventDisableTiming);
        cudaEventCreateWithFlags(&evRes3, cudaEventDisableTiming);
    }

    dim3 mma_grid(2, (N + 127) / 128);
    dim3 mma_grid64(1, (N + 127) / 128);
    dim3 gemm_grid_64(1, (N + BM - 1) / BM);
    int bn_blocks = (N + 255) / 256;
    int sc_blocks = (N + 255) / 256;
    long long tot256 = (long long)N * 256;
    const int SLOT = 256 * 768;

    // ---- setup + fork ----
    k_init<<<gb(N, 256), 256>>>(N);
    cudaEventRecord(evSetup, 0);
    cudaStreamWaitEvent(s1, evSetup, 0);
    cudaStreamWaitEvent(s2, evSetup, 0);

    // s1: CSR build (3-phase scan) + fused layer4 weights
    k_hist<<<gb(E, 256), 256, 0, s1>>>(ei, E);
    k_dinv<<<gb(N, 256), 256, 0, s1>>>(N);
    k_scan1<<<sc_blocks, 256, 0, s1>>>(N);
    k_scan2<<<1, 256, 0, s1>>>(sc_blocks, N);
    k_scan3<<<gb(N, 256), 256, 0, s1>>>(N);
    k_fill<<<gb(E, 256), 256, 0, s1>>>(ei, E);
    k_w4comb<<<17, 64, 0, s1>>>(W4, pW, b4, pb);
    cudaEventRecord(evCSR, s1);

    // s2: residual-path weight splits
    k_buildB<<<256, 256, 0, s2>>>(r1W, Bt2 + 1 * SLOT);
    k_buildB<<<256, 256, 0, s2>>>(Wg, Bt2 + 2 * SLOT);
    k_buildB64<<<128, 256, 0, s2>>>(r2W, Bt2 + 3 * SLOT);

    // s0: main-path splits + h1
    k_buildB<<<256, 256>>>(W1, Bt2 + 0 * SLOT);
    k_buildA<<<gb(tot256, 256), 256>>>(x, A2, tot256);
    cudaEventRecord(evA, 0);

    cudaStreamWaitEvent(s2, evA, 0);
    k_mma_gemm<<<mma_grid, 256, 0, s2>>>(A2, Bt2 + 1 * SLOT, r1b, P3, N, 256);  // res1
    cudaEventRecord(evRes1, s2);

    k_mma_gemm<<<mma_grid, 256>>>(A2, Bt2 + 0 * SLOT, nullptr, P0, N, 256);     // h1

    // ---- layer 1 ----
    cudaStreamWaitEvent(0, evCSR, 0);
    k_gcn_gather<256><<<gb((long long)N * 32, 256), 256>>>(P0, b1, P1, N);
    k_bn_stats<<<bn_blocks, 256>>>(P1, bnsum + 0, bnsq + 0, N, 256);
    k_bn_finalize<<<1, 256>>>(g1, be1, bnsum + 0, bnsq + 0, bnscale + 0, bnshift + 0, invn, 256);
    cudaStreamWaitEvent(0, evRes1, 0);
    k_bn_apply_add_split<<<gb(tot256, 256), 256>>>(P1, P3, bnscale + 0, bnshift + 0, A2, tot256);
    cudaEventRecord(evX2, 0);

    // ---- layer 2 ----
    cudaStreamWaitEvent(s2, evX2, 0);
    k_mma_gemm<<<mma_grid64, 256, 0, s2>>>(A2, Bt2 + 3 * SLOT, r2b, P1, N, 64);  // res2
    cudaEventRecord(evRes2, s2);

    k_mma_gemm<<<mma_grid, 256>>>(A2, Bt2 + 2 * SLOT, nullptr, P0, N, 256);      // h2
    k_gat_logits<<<gb((long long)N * 32, 256), 256>>>(P0, a_s, a_d, N);
    k_gat_gather<<<gb((long long)N * 32, 256), 256>>>(P0, bg, P3, N);            // out2pre
    k_bn_stats<<<bn_blocks, 64>>>(P3, bnsum + 256, bnsq + 256, N, 64);
    k_bn_finalize<<<1, 64>>>(g2, be2, bnsum + 256, bnsq + 256, bnscale + 256, bnshift + 256, invn, 64);
    cudaStreamWaitEvent(0, evRes2, 0);
    k_bn_apply_add<<<gb((long long)N * 64, 256), 256>>>(P3, P1, bnscale + 256, bnshift + 256,
                                                        P0, (long long)N * 64, 64);  // x3
    cudaEventRecord(evX3, 0);

    // ---- layer 3 ----
    cudaStreamWaitEvent(s2, evX3, 0);
    k_sgemm<<<gemm_grid_64, 256, 0, s2>>>(P0, r3W, r3b, P2, N, 64, 16);          // res3
    cudaEventRecord(evRes3, s2);

    k_sgemm<<<gemm_grid_64, 256>>>(P0, W3, nullptr, P3, N, 64, 16);              // h3
    k_gcn_gather<16><<<gb((long long)N * 4, 256), 256>>>(P3, b3, P1, N);
    k_bn_stats<<<bn_blocks, 16>>>(P1, bnsum + 320, bnsq + 320, N, 16);
    k_bn_finalize<<<1, 32>>>(g3, be3, bnsum + 320, bnsq + 320, bnscale + 320, bnshift + 320, invn, 16);
    cudaStreamWaitEvent(0, evRes3, 0);
    k_bn_apply_add<<<gb((long long)N * 16, 256), 256>>>(P1, P2, bnscale + 320, bnshift + 320,
                                                        P3, (long long)N * 16, 16);  // x4

    // ---- layer 4 + final projection (fused: (A_hat x4) @ W4p + b4p) ----
    k_gcn_gather<16><<<gb((long long)N * 4, 256), 256>>>(P3, nullptr, P0, N);
    k_sgemm<<<gemm_grid_64, 256>>>(P0, W4p, b4p, out, N, 16, 64);
}